// round 1
// baseline (speedup 1.0000x reference)
#include <cuda_runtime.h>

#define NN 50000
#define EE 800000
#define F  64        // in feats
#define KK 256       // F * K(=4) = GEMM K dim
#define OF 256       // out feats

// ---- scratch (static __device__ arrays; no allocation allowed) ----
__device__ float g_dsq[NN];                 // deg accumulator, then rsqrt(max(deg,1))
__device__ float g_y[NN * F];               // X_k * d_sqrt (scatter source)
__device__ float g_agg[NN * F];             // scatter destination
__device__ float g_Xt[(size_t)NN * KK];     // packed [X0 | X1 | X2 | X3]

// ---------------- degree ----------------
__global__ void zero_dsq_kernel() {
    int i = blockIdx.x * blockDim.x + threadIdx.x;
    if (i < NN) g_dsq[i] = 0.0f;
}

__global__ void deg_kernel(const int* __restrict__ dst, int E) {
    int e = blockIdx.x * blockDim.x + threadIdx.x;
    if (e < E) atomicAdd(&g_dsq[dst[e]], 1.0f);
}

__global__ void dsqrt_kernel() {
    int i = blockIdx.x * blockDim.x + threadIdx.x;
    if (i < NN) g_dsq[i] = rsqrtf(fmaxf(g_dsq[i], 1.0f));
}

// ---------------- init: X0 into Xt chunk0, y0 = X0 * dsq ----------------
__global__ void init_kernel(const float* __restrict__ sig) {
    int i = blockIdx.x * blockDim.x + threadIdx.x;
    if (i >= NN * F) return;
    int row = i >> 6;
    int f   = i & 63;
    float x = sig[i];
    g_Xt[(size_t)row * KK + f] = x;
    g_y[i] = x * g_dsq[row];
}

__global__ void zero_agg_kernel() {
    int i = blockIdx.x * blockDim.x + threadIdx.x;
    if (i < NN * F) g_agg[i] = 0.0f;
}

// ---------------- edge scatter: agg[dst] += y[src] (vec4 red) ----------------
__global__ void scatter_kernel(const int* __restrict__ src,
                               const int* __restrict__ dst, int E) {
    int idx = blockIdx.x * blockDim.x + threadIdx.x;
    int e = idx >> 4;      // 16 threads per edge
    int j = idx & 15;      // which float4 of the 64-float row
    if (e >= E) return;
    int s = src[e];
    int d = dst[e];
    float4 v = ((const float4*)g_y)[(size_t)s * 16 + j];
    float* p = g_agg + (size_t)d * F + j * 4;
    asm volatile("red.global.add.v4.f32 [%0], {%1,%2,%3,%4};"
                 :: "l"(p), "f"(v.x), "f"(v.y), "f"(v.z), "f"(v.w)
                 : "memory");
}

// ---------------- Chebyshev combine ----------------
// step==1: X1 = -r*L + (r-1)*X0
// step>=2: Xk = -2r*L + 2(r-1)*X_{k-1} - X_{k-2}
// Also writes y = Xk * dsq for the next scatter (if write_y).
__global__ void combine_kernel(const float* __restrict__ lam,
                               int out_off, int p1_off, int p2_off,
                               int step, int write_y) {
    int i = blockIdx.x * blockDim.x + threadIdx.x;
    if (i >= NN * F) return;
    float r = 2.0f / lam[0];
    int row = i >> 6;
    int f   = i & 63;
    float ds = g_dsq[row];
    float L  = g_agg[i] * ds;
    const float* base = g_Xt + (size_t)row * KK + f;
    float out;
    if (step == 1) {
        out = -r * L + (r - 1.0f) * base[p1_off];
    } else {
        out = -2.0f * r * L + 2.0f * (r - 1.0f) * base[p1_off] - base[p2_off];
    }
    g_Xt[(size_t)row * KK + out_off + f] = out;
    if (write_y) g_y[i] = out * ds;
}

// ---------------- GEMM + bias + ReLU ----------------
// C[M, OF] = relu(Xt[M, KK] @ W[KK, OF] + b),  M = NN
#define BM 128
#define BN 128
#define BKk 8

__global__ __launch_bounds__(256)
void gemm_bias_relu(const float* __restrict__ W, const float* __restrict__ bias,
                    float* __restrict__ C, int M) {
    __shared__ float As[BKk][BM];
    __shared__ float Bs[BKk][BN];

    const float* A = g_Xt;
    int bx = blockIdx.x;   // col tile (0..OF/BN-1)
    int by = blockIdx.y;   // row tile
    int tid = threadIdx.x;
    int tr = tid >> 4;     // 0..15
    int tc = tid & 15;     // 0..15

    float acc[8][8];
#pragma unroll
    for (int i = 0; i < 8; i++)
#pragma unroll
        for (int j = 0; j < 8; j++) acc[i][j] = 0.0f;

    int arow = tid >> 1;            // 0..127
    int acol = (tid & 1) * 4;       // 0 or 4
    int brow = tid >> 5;            // 0..7
    int bcol = (tid & 31) * 4;      // 0..124
    int gArow = by * BM + arow;

    for (int k0 = 0; k0 < KK; k0 += BKk) {
        float4 av = make_float4(0.f, 0.f, 0.f, 0.f);
        if (gArow < M)
            av = *(const float4*)(A + (size_t)gArow * KK + k0 + acol);
        As[acol + 0][arow] = av.x;
        As[acol + 1][arow] = av.y;
        As[acol + 2][arow] = av.z;
        As[acol + 3][arow] = av.w;

        float4 bv = *(const float4*)(W + (size_t)(k0 + brow) * OF + bx * BN + bcol);
        *(float4*)&Bs[brow][bcol] = bv;
        __syncthreads();

#pragma unroll
        for (int k = 0; k < BKk; k++) {
            float ra[8], rb[8];
#pragma unroll
            for (int i = 0; i < 8; i++) ra[i] = As[k][tr * 8 + i];
#pragma unroll
            for (int j = 0; j < 8; j++) rb[j] = Bs[k][tc * 8 + j];
#pragma unroll
            for (int i = 0; i < 8; i++)
#pragma unroll
                for (int j = 0; j < 8; j++) acc[i][j] += ra[i] * rb[j];
        }
        __syncthreads();
    }

#pragma unroll
    for (int i = 0; i < 8; i++) {
        int row = by * BM + tr * 8 + i;
        if (row >= M) continue;
#pragma unroll
        for (int j = 0; j < 8; j += 4) {
            int col = bx * BN + tc * 8 + j;
            float4 o;
            o.x = fmaxf(acc[i][j + 0] + bias[col + 0], 0.0f);
            o.y = fmaxf(acc[i][j + 1] + bias[col + 1], 0.0f);
            o.z = fmaxf(acc[i][j + 2] + bias[col + 2], 0.0f);
            o.w = fmaxf(acc[i][j + 3] + bias[col + 3], 0.0f);
            *(float4*)(C + (size_t)row * OF + col) = o;
        }
    }
}

// ---------------- launch ----------------
extern "C" void kernel_launch(void* const* d_in, const int* in_sizes, int n_in,
                              void* d_out, int out_size) {
    const float* signal = (const float*)d_in[0];
    const int*   src    = (const int*)d_in[1];
    const int*   dst    = (const int*)d_in[2];
    const float* lam    = (const float*)d_in[3];
    const float* W      = (const float*)d_in[4];
    const float* b      = (const float*)d_in[5];
    float* out = (float*)d_out;

    const int E = in_sizes[1];
    const int NFB = (NN * F + 255) / 256;     // node-feature grid
    const int EB  = (E + 255) / 256;
    const int SB  = (E * 16 + 255) / 256;     // scatter grid (16 thr/edge)

    // degrees
    zero_dsq_kernel<<<(NN + 255) / 256, 256>>>();
    deg_kernel<<<EB, 256>>>(dst, E);
    dsqrt_kernel<<<(NN + 255) / 256, 256>>>();

    // X0, y0
    init_kernel<<<NFB, 256>>>(signal);

    // X1
    zero_agg_kernel<<<NFB, 256>>>();
    scatter_kernel<<<SB, 256>>>(src, dst, E);
    combine_kernel<<<NFB, 256>>>(lam, /*out*/64, /*p1*/0, /*p2*/0, 1, 1);

    // X2
    zero_agg_kernel<<<NFB, 256>>>();
    scatter_kernel<<<SB, 256>>>(src, dst, E);
    combine_kernel<<<NFB, 256>>>(lam, /*out*/128, /*p1*/64, /*p2*/0, 2, 1);

    // X3
    zero_agg_kernel<<<NFB, 256>>>();
    scatter_kernel<<<SB, 256>>>(src, dst, E);
    combine_kernel<<<NFB, 256>>>(lam, /*out*/192, /*p1*/128, /*p2*/64, 2, 0);

    // out = relu(Xt @ W + b)
    dim3 grid(OF / BN, (NN + BM - 1) / BM);
    gemm_bias_relu<<<grid, 256>>>(W, b, out, NN);
}